// round 9
// baseline (speedup 1.0000x reference)
#include <cuda_runtime.h>
#include <cstdint>

// Matrices are 8192 x 8192 fp32. offset = (x << 13) | y, 26 bits.
#define ROW_SHIFT 13
#define NBUCK     32
#define BUCK_SHIFT 21            // bucket = offset >> 21 (256 rows per bucket)
#define CAPLOG    19
#define CAP       (1u << CAPLOG) // 524288 slots per bucket (mean ~328K, huge slack)
#define CHUNK     4096
#define FLAG_NEG  0x80000000u
#define OFF_MASK  0x03FFFFFFu

// Bucketed packed-index lists: bucket b occupies g_list[b<<CAPLOG .. +CAP). 64 MB.
__device__ unsigned g_list[NBUCK << CAPLOG];
__device__ unsigned g_cursor[NBUCK];
// Accumulators: [0]=pos, [1]=neg, plus completion counter (zeroed each replay).
__device__ double g_acc[2];
__device__ unsigned g_done;

// ─────────────────────────── Zero (per replay) ──────────────────────────────
__global__ void zero_kernel() {
    int t = threadIdx.x;
    if (t < NBUCK) g_cursor[t] = 0u;
    if (t == NBUCK) { g_acc[0] = 0.0; g_acc[1] = 0.0; g_done = 0u; }
}

// ─────────────── Partition: pack (x,y)+flag, bucket by row range ────────────
// Per-chunk smem counting sort -> coalesced reads AND coalesced bucket writes.
__global__ void __launch_bounds__(256) partition_kernel(
    const int* __restrict__ xi, const int* __restrict__ yi,
    int n, unsigned flag)
{
    __shared__ unsigned s_elems[CHUNK];    // unsorted packed
    __shared__ unsigned s_sorted[CHUNK];   // bucket-grouped packed
    __shared__ unsigned s_cnt[NBUCK];
    __shared__ unsigned s_off[NBUCK];
    __shared__ unsigned s_rank[NBUCK];
    __shared__ unsigned s_gbase[NBUCK];

    const int tid = threadIdx.x;
    const int chunk_base = blockIdx.x * CHUNK;
    if (chunk_base >= n) return;
    const int m = min(CHUNK, n - chunk_base);

    if (tid < NBUCK) s_cnt[tid] = 0u;
    __syncthreads();

    // pass 1: load (int4-coalesced), pack, stage, count
    const int4* x4 = reinterpret_cast<const int4*>(xi + chunk_base);
    const int4* y4 = reinterpret_cast<const int4*>(yi + chunk_base);
    const int nv = m >> 2;
    for (int i = tid; i < nv; i += 256) {
        int4 xv = __ldcs(&x4[i]);
        int4 yv = __ldcs(&y4[i]);
        unsigned p0 = (((unsigned)xv.x << ROW_SHIFT) | (unsigned)yv.x) | flag;
        unsigned p1 = (((unsigned)xv.y << ROW_SHIFT) | (unsigned)yv.y) | flag;
        unsigned p2 = (((unsigned)xv.z << ROW_SHIFT) | (unsigned)yv.z) | flag;
        unsigned p3 = (((unsigned)xv.w << ROW_SHIFT) | (unsigned)yv.w) | flag;
        s_elems[4 * i + 0] = p0;
        s_elems[4 * i + 1] = p1;
        s_elems[4 * i + 2] = p2;
        s_elems[4 * i + 3] = p3;
        atomicAdd(&s_cnt[(p0 >> BUCK_SHIFT) & (NBUCK - 1)], 1u);
        atomicAdd(&s_cnt[(p1 >> BUCK_SHIFT) & (NBUCK - 1)], 1u);
        atomicAdd(&s_cnt[(p2 >> BUCK_SHIFT) & (NBUCK - 1)], 1u);
        atomicAdd(&s_cnt[(p3 >> BUCK_SHIFT) & (NBUCK - 1)], 1u);
    }
    for (int i = (nv << 2) + tid; i < m; i += 256) {   // scalar tail
        unsigned pk = (((unsigned)xi[chunk_base + i] << ROW_SHIFT)
                     | (unsigned)yi[chunk_base + i]) | flag;
        s_elems[i] = pk;
        atomicAdd(&s_cnt[(pk >> BUCK_SHIFT) & (NBUCK - 1)], 1u);
    }
    __syncthreads();

    // scan + reserve global space (warp 0)
    if (tid < 32) {
        unsigned c = s_cnt[tid];
        unsigned x = c;
        #pragma unroll
        for (int d = 1; d < 32; d <<= 1) {
            unsigned v = __shfl_up_sync(0xFFFFFFFFu, x, d);
            if (tid >= d) x += v;
        }
        s_off[tid]  = x - c;            // exclusive prefix
        s_rank[tid] = 0u;
        s_gbase[tid] = atomicAdd(&g_cursor[tid], c);
    }
    __syncthreads();

    // pass 2: group by bucket inside smem
    for (int j = tid; j < m; j += 256) {
        unsigned pk = s_elems[j];
        unsigned b  = (pk >> BUCK_SHIFT) & (NBUCK - 1);
        unsigned r  = atomicAdd(&s_rank[b], 1u);
        s_sorted[s_off[b] + r] = pk;
    }
    __syncthreads();

    // pass 3: coalesced write-out (consecutive j in a bucket -> consecutive dst)
    for (int j = tid; j < m; j += 256) {
        unsigned pk   = s_sorted[j];
        unsigned b    = (pk >> BUCK_SHIFT) & (NBUCK - 1);
        unsigned slot = s_gbase[b] + ((unsigned)j - s_off[b]);
        if (slot < CAP)                 // overflow guard (cannot trigger on uniform data)
            g_list[(b << CAPLOG) + slot] = pk;
    }
}

// ───────── Gather: walk buckets in order; R,P window per bucket ~ L2 ────────
__global__ void __launch_bounds__(256) gather_loss_kernel(
    const float* __restrict__ R, const float* __restrict__ P,
    const float* __restrict__ alpha, float* __restrict__ out)
{
    const int tid    = blockIdx.x * blockDim.x + threadIdx.x;
    const int stride = gridDim.x * blockDim.x;

    float accp = 0.0f, accn = 0.0f;

    for (int b = 0; b < NBUCK; b++) {
        unsigned nb = g_cursor[b];
        if (nb > CAP) nb = CAP;
        const unsigned* lst = g_list + ((unsigned)b << CAPLOG);
        const uint4* l4 = reinterpret_cast<const uint4*>(lst);
        const unsigned nv = nb >> 3;                 // 8 packed per iteration

        for (unsigned i = tid; i < nv; i += stride) {
            uint4 a = __ldcs(&l4[2 * i]);
            uint4 c = __ldcs(&l4[2 * i + 1]);

            unsigned o0 = a.x & OFF_MASK, o1 = a.y & OFF_MASK;
            unsigned o2 = a.z & OFF_MASK, o3 = a.w & OFF_MASK;
            unsigned o4 = c.x & OFF_MASK, o5 = c.y & OFF_MASK;
            unsigned o6 = c.z & OFF_MASK, o7 = c.w & OFF_MASK;

            // 16 gathers in flight before any consumption.
            float r0 = __ldg(R + o0);
            float r1 = __ldg(R + o1);
            float r2 = __ldg(R + o2);
            float r3 = __ldg(R + o3);
            float r4 = __ldg(R + o4);
            float r5 = __ldg(R + o5);
            float r6 = __ldg(R + o6);
            float r7 = __ldg(R + o7);
            float p0 = __ldg(P + o0);
            float p1 = __ldg(P + o1);
            float p2 = __ldg(P + o2);
            float p3 = __ldg(P + o3);
            float p4 = __ldg(P + o4);
            float p5 = __ldg(P + o5);
            float p6 = __ldg(P + o6);
            float p7 = __ldg(P + o7);

            float d0 = r0 - p0, d1 = r1 - p1, d2 = r2 - p2, d3 = r3 - p3;
            float d4 = r4 - p4, d5 = r5 - p5, d6 = r6 - p6, d7 = r7 - p7;
            float s0 = d0 * d0, s1 = d1 * d1, s2 = d2 * d2, s3 = d3 * d3;
            float s4 = d4 * d4, s5 = d5 * d5, s6 = d6 * d6, s7 = d7 * d7;

            accp += (a.x & FLAG_NEG) ? 0.0f : s0;
            accn += (a.x & FLAG_NEG) ? s0 : 0.0f;
            accp += (a.y & FLAG_NEG) ? 0.0f : s1;
            accn += (a.y & FLAG_NEG) ? s1 : 0.0f;
            accp += (a.z & FLAG_NEG) ? 0.0f : s2;
            accn += (a.z & FLAG_NEG) ? s2 : 0.0f;
            accp += (a.w & FLAG_NEG) ? 0.0f : s3;
            accn += (a.w & FLAG_NEG) ? s3 : 0.0f;
            accp += (c.x & FLAG_NEG) ? 0.0f : s4;
            accn += (c.x & FLAG_NEG) ? s4 : 0.0f;
            accp += (c.y & FLAG_NEG) ? 0.0f : s5;
            accn += (c.y & FLAG_NEG) ? s5 : 0.0f;
            accp += (c.z & FLAG_NEG) ? 0.0f : s6;
            accn += (c.z & FLAG_NEG) ? s6 : 0.0f;
            accp += (c.w & FLAG_NEG) ? 0.0f : s7;
            accn += (c.w & FLAG_NEG) ? s7 : 0.0f;
        }
        for (unsigned i = (nv << 3) + tid; i < nb; i += stride) {   // tail
            unsigned pk = __ldcs(lst + i);
            unsigned o  = pk & OFF_MASK;
            float d = __ldg(R + o) - __ldg(P + o);
            float s = d * d;
            accp += (pk & FLAG_NEG) ? 0.0f : s;
            accn += (pk & FLAG_NEG) ? s : 0.0f;
        }
    }

    // Block reduce in double.
    double dp = (double)accp;
    double dn = (double)accn;
    #pragma unroll
    for (int off = 16; off > 0; off >>= 1) {
        dp += __shfl_down_sync(0xFFFFFFFFu, dp, off);
        dn += __shfl_down_sync(0xFFFFFFFFu, dn, off);
    }

    __shared__ double smem_p[8];
    __shared__ double smem_n[8];
    const int lane = threadIdx.x & 31;
    const int warp = threadIdx.x >> 5;
    if (lane == 0) { smem_p[warp] = dp; smem_n[warp] = dn; }
    __syncthreads();

    __shared__ bool is_last;
    if (warp == 0) {
        const int nwarps = blockDim.x >> 5;
        dp = (lane < nwarps) ? smem_p[lane] : 0.0;
        dn = (lane < nwarps) ? smem_n[lane] : 0.0;
        #pragma unroll
        for (int off = 4; off > 0; off >>= 1) {
            dp += __shfl_down_sync(0xFFu, dp, off);
            dn += __shfl_down_sync(0xFFu, dn, off);
        }
        if (lane == 0) {
            atomicAdd(&g_acc[0], dp);
            atomicAdd(&g_acc[1], dn);
            __threadfence();
            unsigned t = atomicAdd(&g_done, 1u);
            is_last = (t == gridDim.x - 1);
        }
    }
    __syncthreads();

    if (is_last && threadIdx.x == 0) {
        double ps = g_acc[0];
        double ns = g_acc[1];
        float a = alpha[0];
        out[0] = (float)(ps * (double)((1.0f - a) * 0.5f)
                       + ns * (double)(a * 0.5f));
    }
}

extern "C" void kernel_launch(void* const* d_in, const int* in_sizes, int n_in,
                              void* d_out, int out_size)
{
    const float* R     = (const float*)d_in[0];   // drug_protein_reconstruct
    const float* P     = (const float*)d_in[1];   // drug_protein
    const float* alpha = (const float*)d_in[2];
    const int*   pos_x = (const int*)d_in[3];
    const int*   pos_y = (const int*)d_in[4];
    const int*   neg_x = (const int*)d_in[5];
    const int*   neg_y = (const int*)d_in[6];

    const int n_pos = in_sizes[3];
    const int n_neg = in_sizes[5];

    float* out = (float*)d_out;

    zero_kernel<<<1, 64>>>();

    const int pos_chunks = (n_pos + CHUNK - 1) / CHUNK;
    const int neg_chunks = (n_neg + CHUNK - 1) / CHUNK;
    partition_kernel<<<pos_chunks, 256>>>(pos_x, pos_y, n_pos, 0u);
    partition_kernel<<<neg_chunks, 256>>>(neg_x, neg_y, n_neg, FLAG_NEG);

    gather_loss_kernel<<<148 * 8, 256>>>(R, P, alpha, out);
}